// round 17
// baseline (speedup 1.0000x reference)
#include <cuda_runtime.h>
#include <cuda_bf16.h>
#include <cuda_fp16.h>
#include <mma.h>

using namespace nvcuda;

#define N_NODES 50000
#define N_EDGES 800000
#define D 64
#define PAD 64                       // padded CSR row capacity (multiple of 8)
#define TILE_NODES 32
#define N_TILES ((N_NODES + TILE_NODES - 1) / TILE_NODES)   // 1563 (last tile: 16 valid)
#define LDA 72                       // sAh row stride in halfs (144B, 16B-aligned rows)
#define LDI 68                       // sIdx row stride in ints (272B -> conflict-free groups)
#define EDGE_BLOCKS (N_EDGES / 256)  // 3125, exact: one edge per thread

// Scratch (device globals — no allocation allowed). Zero-initialized at load;
// fused_kernel re-zeroes the counters it consumed, so every call (incl. graph
// replays) sees zeroed counters.
__device__ int     g_outdeg[N_NODES];
__device__ int     g_cursor[N_NODES];      // in-degree counter / row fill
__device__ float   g_scale_dst[N_NODES];   // rsqrt(max(indeg,1))
__device__ int     g_sorted_src[N_NODES * PAD];
__device__ __half2 g_h2[(N_NODES + 1) * (D / 2)];  // h = x*scale_src (fp16); last row zeros
__device__ __half  g_W16[D * D];                   // W quantized to fp16

__device__ __forceinline__ int load_idx(const void* __restrict__ p, int i, int is64) {
    if (is64) return (int)(((const long long*)p)[i]);
    return ((const int*)p)[i];
}

// ---------------------------------------------------------------------------
// prep_a: index-dtype detect (per block) + single edge pass (1 edge/thread):
// bin by dst (cursor atomic doubles as in-degree), RED out-degree.
// Also: W fp16 conversion + sentinel h2 row (independent side work).
__global__ void __launch_bounds__(256) prep_a_kernel(const float* __restrict__ W,
                                                     const void* __restrict__ src,
                                                     const void* __restrict__ dst) {
    __shared__ int s_bad;
    int tid = blockIdx.x * 256 + threadIdx.x;

    // Per-block index-dtype detection (64 probe loads, L2-broadcast friendly).
    if (threadIdx.x == 0) s_bad = 0;
    __syncthreads();
    if (threadIdx.x < 64) {
        long long v = ((const long long*)src)[threadIdx.x];
        if (v < 0 || v >= (long long)N_NODES) atomicOr(&s_bad, 1);
    }
    __syncthreads();
    int is64 = s_bad ? 0 : 1;

    if (blockIdx.x == 0 && threadIdx.x < 32)
        g_h2[N_NODES * 32 + threadIdx.x] = __floats2half2_rn(0.f, 0.f);
    if (tid < D * D) g_W16[tid] = __float2half(W[tid]);

    // One edge per thread.
    int s = load_idx(src, tid, is64);
    int d = load_idx(dst, tid, is64);
    atomicAdd(&g_outdeg[s], 1);                     // no return -> RED
    int pos = atomicAdd(&g_cursor[d], 1);
    if (pos < PAD) g_sorted_src[d * PAD + pos] = s;
}

// ---------------------------------------------------------------------------
// prep_b: dst scales + sentinel padding to 8-multiple + h16 conversion.
__global__ void __launch_bounds__(256) prep_b_kernel(const float* __restrict__ x) {
    int tid = blockIdx.x * 256 + threadIdx.x;

    if (tid < N_NODES) {
        int cnt = g_cursor[tid];
        g_scale_dst[tid] = rsqrtf(fmaxf((float)cnt, 1.0f));
        int deg = cnt < PAD ? cnt : PAD;
        int end = (deg + 7) & ~7;
        if (end > PAD) end = PAD;
        for (int p = deg; p < end; p++) g_sorted_src[tid * PAD + p] = N_NODES;
    }

    // h = x * rsqrt(max(outdeg,1)) in fp16; one float4 (4 elems) per thread.
    if (tid < N_NODES * (D / 4)) {
        int node = tid >> 4;
        float sc = rsqrtf(fmaxf((float)g_outdeg[node], 1.0f));
        float4 v = ((const float4*)x)[tid];
        g_h2[tid * 2]     = __floats2half2_rn(v.x * sc, v.y * sc);
        g_h2[tid * 2 + 1] = __floats2half2_rn(v.z * sc, v.w * sc);
    }
}

// ---------------------------------------------------------------------------
// Fused pull + tensor-core GEMM. 32 nodes per block. Each warp stages its 4
// nodes' CSR rows into shared (conflict-free LDI stride), then processes the
// 4 nodes simultaneously (8 lanes per node; one LDG.128 covers a full 128B h2
// row) reading indices via broadcast LDS — no shfl. Sentinel chunks predicated
// OFF, pair accumulation via HADD2. Then each warp computes one 16x16 wmma
// tile (fp16->fp32) with bias preloaded.
__global__ void __launch_bounds__(256, 7) fused_kernel(const float* __restrict__ b,
                                                       float* __restrict__ out) {
    __shared__ __align__(16) __half sW16[D * D];           // [k][n], ld=64
    __shared__ __align__(16) __half sAh[TILE_NODES * LDA]; // [node][k], ld=72
    __shared__ float sBias[16 * D];                        // 16 rows of bias
    __shared__ __align__(16) int sIdx[TILE_NODES * LDI];   // staged CSR rows

    int tid  = threadIdx.x;
    int w    = tid >> 5;
    int lane = tid & 31;
    int grp  = lane >> 3;          // 0..3 : node group within warp
    int subl = lane & 7;           // 0..7 : 16B slice of the 128B row
    int base = blockIdx.x * TILE_NODES;

    // Stage W16 (4096 halfs = 512 float4) and bias tile.
#pragma unroll
    for (int i = 0; i < 2; i++)
        ((float4*)sW16)[tid + i * 256] = ((const float4*)g_W16)[tid + i * 256];
#pragma unroll
    for (int i = 0; i < 4; i++) {
        int idx = tid + i * 256;
        sBias[idx] = b[idx & 63];
    }

    // Stage this warp's 4 CSR rows into sIdx (coalesced; clamp OOB nodes).
#pragma unroll
    for (int i = 0; i < 4; i++) {
        int n = base + w * 4 + i;
        int nc = n < N_NODES ? n : N_NODES - 1;     // clamp (unused rows)
        if (lane < 16) {
            int4 v = ((const int4*)(g_sorted_src + nc * PAD))[lane];
            *(int4*)(sIdx + (w * 4 + i) * LDI + lane * 4) = v;
        }
    }
    __syncwarp();

    const int4* __restrict__ h4 = (const int4*)g_h2;   // row n = int4s [n*8, n*8+8)

    // Gather: warp w handles nodes base + w*4 .. +3 (one per 8-lane group).
    {
        int n = base + w * 4 + grp;
        bool valid = (n < N_NODES);
        int deg = valid ? g_cursor[n] : 0;
        if (deg > PAD) deg = PAD;
        int chunks = (deg + 7) >> 3;
        int cmax = __reduce_max_sync(0xffffffffu, chunks);
        const int* __restrict__ myrow = sIdx + (w * 4 + grp) * LDI;

        float acc[8];
#pragma unroll
        for (int i = 0; i < 8; i++) acc[i] = 0.f;

        for (int c = 0; c < cmax; c++) {
            bool live = (c < chunks);         // uniform within the 8-lane group
#pragma unroll
            for (int e = 0; e < 8; e += 2) {
                int s0 = myrow[c * 8 + e];        // broadcast LDS
                int s1 = myrow[c * 8 + e + 1];
                if (live) {                   // predicated: no wavefronts when done
                    int4 v0 = h4[s0 * 8 + subl];
                    int4 v1 = h4[s1 * 8 + subl];
                    __half2* a0 = (__half2*)&v0;
                    __half2* a1 = (__half2*)&v1;
#pragma unroll
                    for (int q = 0; q < 4; q++) {
                        float2 f = __half22float2(__hadd2(a0[q], a1[q]));
                        acc[2 * q]     += f.x;
                        acc[2 * q + 1] += f.y;
                    }
                }
            }
        }

        float scd = valid ? g_scale_dst[n] : 1.0f;
        __half2 hout[4];
#pragma unroll
        for (int i = 0; i < 4; i++)
            hout[i] = __floats2half2_rn(acc[2 * i] * scd, acc[2 * i + 1] * scd);
        *(int4*)(sAh + (w * 4 + grp) * LDA + subl * 8) = *(int4*)hout;
    }
    __syncthreads();

    // Zero this tile's counters for the next call (reads above are done).
    if (tid < TILE_NODES) {
        int node = base + tid;
        if (node < N_NODES) { g_cursor[node] = 0; g_outdeg[node] = 0; }
    }

    // wmma GEMM: warp w -> m-slab (w&1, 16 rows), n-quarter (w>>1, 16 cols).
    int m_slab = w & 1;
    int n_off  = (w >> 1) * 16;
    int row0   = base + m_slab * 16;
    if (row0 < N_NODES) {            // 50000 % 16 == 0 -> slab fully valid
        wmma::fragment<wmma::accumulator, 16, 16, 16, float> acc0;
        wmma::load_matrix_sync(acc0, sBias + n_off, D, wmma::mem_row_major);
#pragma unroll
        for (int k = 0; k < 4; k++) {
            wmma::fragment<wmma::matrix_a, 16, 16, 16, __half, wmma::row_major> fa;
            wmma::load_matrix_sync(fa, sAh + (m_slab * 16) * LDA + k * 16, LDA);
            wmma::fragment<wmma::matrix_b, 16, 16, 16, __half, wmma::row_major> fb0;
            wmma::load_matrix_sync(fb0, sW16 + (k * 16) * D + n_off, D);
            wmma::mma_sync(acc0, fa, fb0, acc0);
        }
        wmma::store_matrix_sync(out + (size_t)row0 * D + n_off, acc0, D, wmma::mem_row_major);
    }
}

// ---------------------------------------------------------------------------
extern "C" void kernel_launch(void* const* d_in, const int* in_sizes, int n_in,
                              void* d_out, int out_size) {
    const float* x   = (const float*)d_in[0];
    const void*  src = d_in[1];
    const void*  dst = d_in[2];
    const float* W   = (const float*)d_in[3];
    const float* b   = (const float*)d_in[4];
    float* out = (float*)d_out;

    prep_a_kernel<<<EDGE_BLOCKS, 256>>>(W, src, dst);
    prep_b_kernel<<<EDGE_BLOCKS, 256>>>(x);
    fused_kernel<<<N_TILES, 256>>>(b, out);
}